// round 9
// baseline (speedup 1.0000x reference)
#include <cuda_runtime.h>
#include <cuda_fp16.h>
#include <stdint.h>

// AllZeroDigitalFilter via fp16 tensor cores, thin-warp decomposition.
// Block covers 160 outputs (2 segments of P=80); warp w (0..9) computes m-tile w
// (16 outputs) via mma.sync.m16n8k16: C[16x8] = A[16x256] * B[256x8], where
// A[r,k] = x[T0 + r - k] (Toeplitz) and B cols = [h0_hi, d_hi, h0_lo, d_lo, 0..0]
// for the warp's segment. Compensated fp16: accH = A_hi*B, accL = A_lo*B;
// y = (Ahi+Alo)(Bhi+Blo) via column sums in the epilogue.
// out[p] = y0[p] + (p/80)*y1[p].

#define NB   800
#define PP   80
#define TAPS 256
#define TT   (NB * PP)
#define NTH  320
#define RPB  160          // outputs per block
#define APAD 211

__device__ __forceinline__ uint32_t packh2(__half lo, __half hi) {
    __half2 t = __halves2half2(lo, hi);
    return *reinterpret_cast<uint32_t*>(&t);
}

__device__ __forceinline__ void mma16816(float* c,
    uint32_t a0, uint32_t a1, uint32_t a2, uint32_t a3,
    uint32_t b0, uint32_t b1)
{
    asm volatile(
        "mma.sync.aligned.m16n8k16.row.col.f32.f16.f16.f32 "
        "{%0,%1,%2,%3}, {%4,%5,%6,%7}, {%8,%9}, {%0,%1,%2,%3};"
        : "+f"(c[0]), "+f"(c[1]), "+f"(c[2]), "+f"(c[3])
        : "r"(a0), "r"(a1), "r"(a2), "r"(a3), "r"(b0), "r"(b1));
}

__global__ __launch_bounds__(NTH)
void azdf_mma(const float* __restrict__ x,
              const float* __restrict__ h,
              float* __restrict__ out)
{
    __shared__ float swf[420];            // reversed x window: swf[i] = x[T0+159-i]
    __shared__ uint2 sA[2][APAD];         // [parity][v]: {hi-pair, lo-pair}
    __shared__ uint2 sB[2][4][17][4];     // [seg][col][ks(+pad)][tg]: {b0, b1}

    const int tid = threadIdx.x;
    const int b   = blockIdx.y;
    const int blk = blockIdx.x;
    const int T0  = blk * RPB;

    // ---- stage reversed window (OOB below 0 -> 0; T0+159 <= 63999 always)
    {
        const float* xb = x + (size_t)b * TT;
        for (int i = tid; i < 420; i += NTH) {
            int gt = T0 + 159 - i;
            swf[i] = (gt >= 0) ? xb[gt] : 0.0f;
        }
    }
    // ---- stage B fragments straight from global (L2-hit heavy)
    // cols: 0 = h0_hi, 1 = d_hi, 2 = h0_lo, 3 = d_lo
    for (int e = tid; e < 512; e += NTH) {
        int tg  = e & 3;
        int ks  = (e >> 2) & 15;
        int col = (e >> 6) & 3;
        int seg = e >> 8;
        int n   = blk * 2 + seg;
        int nn  = (n + 1 < NB) ? (n + 1) : (NB - 1);
        const float* h0p = h + ((size_t)b * NB + n)  * TAPS;
        const float* h1p = h + ((size_t)b * NB + nn) * TAPS;
        const int filt = col & 1, part = col >> 1;
        const int kb = ks * 16 + 2 * tg;
        __half q[4];
        #pragma unroll
        for (int j = 0; j < 4; j++) {
            int k = kb + ((j >> 1) ? 8 : 0) + (j & 1);
            float a = h0p[k];
            float v = filt ? (h1p[k] - a) : a;
            __half vh = __float2half_rn(v);
            q[j] = part ? __float2half_rn(v - __half2float(vh)) : vh;
        }
        sB[seg][col][ks][tg] = make_uint2(packh2(q[0], q[1]), packh2(q[2], q[3]));
    }
    __syncthreads();

    // ---- build fused parity pair arrays: E[v]={w2v,w2v+1}, O[v]={w2v+1,w2v+2}
    for (int v = tid; v < 209; v += NTH) {
        float f0 = swf[2*v], f1 = swf[2*v+1], f2 = swf[2*v+2];
        __half h0 = __float2half_rn(f0), h1 = __float2half_rn(f1), h2 = __float2half_rn(f2);
        __half l0 = __float2half_rn(f0 - __half2float(h0));
        __half l1 = __float2half_rn(f1 - __half2float(h1));
        __half l2 = __float2half_rn(f2 - __half2float(h2));
        sA[0][v] = make_uint2(packh2(h0, h1), packh2(l0, l1));
        sA[1][v] = make_uint2(packh2(h1, h2), packh2(l1, l2));
    }
    __syncthreads();

    // ---- compute: warp w -> m-tile w (rows [16w, 16w+16) of the block)
    const int w    = tid >> 5;
    const int lane = tid & 31;
    const int g    = lane >> 2;
    const int tg   = lane & 3;
    const int seg  = (w >= 5);

    // A pair index: i00 = 159 - 16w - g + 2tg  (>= 8 > 0 always)
    const int i00 = 159 - 16 * w - g + 2 * tg;
    const int ph  = i00 & 1;
    const int v0  = i00 >> 1;
    const uint2* pA = &sA[ph][0];
    const uint2* pB = &sB[seg][g & 3][0][tg];

    float aH[4] = {0.f, 0.f, 0.f, 0.f};
    float aL[4] = {0.f, 0.f, 0.f, 0.f};

    #pragma unroll
    for (int ks = 0; ks < 16; ks++) {
        uint32_t b0 = 0u, b1 = 0u;
        if (g < 4) { uint2 bf = pB[ks * 4]; b0 = bf.x; b1 = bf.y; }
        uint2 A0 = pA[v0 + 8 * ks];
        uint2 A1 = pA[v0 + 8 * ks - 4];
        uint2 A2 = pA[v0 + 8 * ks + 4];
        mma16816(aH, A0.x, A1.x, A2.x, A0.x, b0, b1);
        mma16816(aL, A0.y, A1.y, A2.y, A0.y, b0, b1);
    }

    // ---- epilogue: hi+lo, column combine (y0 = c0+c2, y1 = c1+c3), blend, store
    float t0 = aH[0] + aL[0];
    float t1 = aH[1] + aL[1];
    float t2 = aH[2] + aL[2];
    float t3 = aH[3] + aL[3];
    float s0 = t0 + __shfl_down_sync(0xffffffffu, t0, 1);
    float s1 = t1 + __shfl_down_sync(0xffffffffu, t1, 1);
    float s2 = t2 + __shfl_down_sync(0xffffffffu, t2, 1);
    float s3 = t3 + __shfl_down_sync(0xffffffffu, t3, 1);
    if (tg == 0) {
        const float inv = 1.0f / (float)PP;
        const int rloc = 16 * w + g;          // block-local output row
        const int p    = rloc - PP * seg;     // position within segment
        float* ob = out + (size_t)b * TT + T0;
        ob[rloc]     = s0 + (float)p       * inv * s1;
        ob[rloc + 8] = s2 + (float)(p + 8) * inv * s3;
    }
}

extern "C" void kernel_launch(void* const* d_in, const int* in_sizes, int n_in,
                              void* d_out, int out_size)
{
    const float* x = (const float*)d_in[0];
    const float* h = (const float*)d_in[1];
    float* out = (float*)d_out;
    (void)in_sizes; (void)n_in; (void)out_size;

    dim3 grid(TT / RPB, 8);   // 400 x 8 = 3200 blocks
    azdf_mma<<<grid, NTH>>>(x, h, out);
}

// round 11
// speedup vs baseline: 1.0655x; 1.0655x over previous
#include <cuda_runtime.h>
#include <cuda_fp16.h>
#include <stdint.h>

// AllZeroDigitalFilter via fp16 tensor cores; warp = full segment (80 rows),
// Toeplitz diagonal ring (4 A-frags carried, 1 loaded per k-step).
// C[80x8] = A[80x256] * B[256x8]; A[p,k] = x[n*80+p-k];
// B cols = [h0_hi, d_hi, h0_lo, d_lo, 0..0]; compensated: accH=A_hi*B, accL=A_lo*B.
// out[p] = y0[p] + (p/80)*y1[p],  y0 = col0+col2, y1 = col1+col3.

#define NB   800
#define PP   80
#define TAPS 256
#define TT   (NB * PP)
#define SEGB 8                 // segments (=warps) per block
#define NTH  (SEGB * 32)       // 256
#define WLEN 896               // staged reversed-window floats (need i <= 894)
#define NPAIR 447              // pair entries filled (v <= 446)
#define AP   448               // sA stride per parity (uint2)

__device__ __forceinline__ uint32_t packh2(__half lo, __half hi) {
    __half2 t = __halves2half2(lo, hi);
    return *reinterpret_cast<uint32_t*>(&t);
}

__device__ __forceinline__ void mma16816(float* c,
    uint32_t a0, uint32_t a1, uint32_t a2, uint32_t a3,
    uint32_t b0, uint32_t b1)
{
    asm volatile(
        "mma.sync.aligned.m16n8k16.row.col.f32.f16.f16.f32 "
        "{%0,%1,%2,%3}, {%4,%5,%6,%7}, {%8,%9}, {%0,%1,%2,%3};"
        : "+f"(c[0]), "+f"(c[1]), "+f"(c[2]), "+f"(c[3])
        : "r"(a0), "r"(a1), "r"(a2), "r"(a3), "r"(b0), "r"(b1));
}

__global__ __launch_bounds__(NTH, 2)
void azdf_mma(const float* __restrict__ x,
              const float* __restrict__ h,
              float* __restrict__ out)
{
    __shared__ float swf[WLEN];        // swf[i] = x[blk*640 + 639 - i]
    __shared__ uint2 sA[2][AP];        // [parity][v] : {hi pair, lo pair}
    __shared__ uint2 sB[SEGB][4][17][4];  // [seg][col][ks pad17][tg] : {b0, b1}

    const int tid = threadIdx.x;
    const int b   = blockIdx.y;
    const int blk = blockIdx.x;

    // ---- stage reversed window (OOB -> 0; only blk=0 has OOB)
    {
        const float* xb = x + (size_t)b * TT;
        const int gb = blk * 640 + 639;
        for (int i = tid; i < WLEN; i += NTH) {
            int gt = gb - i;
            swf[i] = (gt >= 0) ? xb[gt] : 0.0f;
        }
    }
    // ---- stage B fragments (cols: 0=h0_hi 1=d_hi 2=h0_lo 3=d_lo)
    for (int e = tid; e < SEGB * 4 * 16 * 4; e += NTH) {
        int tg  = e & 3;
        int ks  = (e >> 2) & 15;
        int col = (e >> 6) & 3;
        int seg = e >> 8;
        int n   = blk * SEGB + seg;
        int nn  = (n + 1 < NB) ? (n + 1) : (NB - 1);
        const float* h0p = h + ((size_t)b * NB + n)  * TAPS;
        const float* h1p = h + ((size_t)b * NB + nn) * TAPS;
        const int filt = col & 1, part = col >> 1;
        const int kb = ks * 16 + 2 * tg;
        __half q[4];
        #pragma unroll
        for (int j = 0; j < 4; j++) {
            int k = kb + ((j >> 1) ? 8 : 0) + (j & 1);
            float a = h0p[k];
            float v = filt ? (h1p[k] - a) : a;
            __half vh = __float2half_rn(v);
            q[j] = part ? __float2half_rn(v - __half2float(vh)) : vh;
        }
        sB[seg][col][ks][tg] = make_uint2(packh2(q[0], q[1]), packh2(q[2], q[3]));
    }
    __syncthreads();

    // ---- fused parity pair arrays: E[v]={w2v,w2v+1}, O[v]={w2v+1,w2v+2}
    for (int v = tid; v < NPAIR; v += NTH) {
        float f0 = swf[2*v], f1 = swf[2*v+1], f2 = swf[2*v+2];
        __half h0 = __float2half_rn(f0), h1 = __float2half_rn(f1), h2 = __float2half_rn(f2);
        __half l0 = __float2half_rn(f0 - __half2float(h0));
        __half l1 = __float2half_rn(f1 - __half2float(h1));
        __half l2 = __float2half_rn(f2 - __half2float(h2));
        sA[0][v] = make_uint2(packh2(h0, h1), packh2(l0, l1));
        sA[1][v] = make_uint2(packh2(h1, h2), packh2(l1, l2));
    }
    __syncthreads();

    // ---- compute: warp w = segment blk*8 + w
    const int w    = tid >> 5;
    const int lane = tid & 31;
    const int g    = lane >> 2;
    const int tg   = lane & 3;

    // A-frag pair index: i0(d) = L0 + 16d, L0 = 639 - 80w - g + 2tg, d = ks - mt
    const int L0 = 639 - PP * w - g + 2 * tg;
    const int ph = L0 & 1;
    const int v0 = L0 >> 1;
    const uint2* pA = &sA[ph][0];
    const uint2* pB = &sB[w][g & 3][0][tg];

    float aH[5][4] = {};
    float aL[5][4] = {};

    // diagonal ring: slot(d) = ((d % 5) + 5) % 5; frag = {R0,R1,R2} (a0,a1,a2)
    uint2 R0[5], R1[5], R2[5];
    #pragma unroll
    for (int d = -4; d <= -1; d++) {
        int sl = (d + 5) % 5;         // slots 1..4
        R0[sl] = pA[v0 + 8 * d];
        R1[sl] = pA[v0 + 8 * d - 4];
        R2[sl] = pA[v0 + 8 * d + 4];
    }

    #pragma unroll
    for (int ks = 0; ks < 16; ks++) {
        const int sl = ks % 5;
        R0[sl] = pA[v0 + 8 * ks];
        R1[sl] = pA[v0 + 8 * ks - 4];
        R2[sl] = pA[v0 + 8 * ks + 4];

        uint32_t b0 = 0u, b1 = 0u;
        if (g < 4) { uint2 bf = pB[ks * 4]; b0 = bf.x; b1 = bf.y; }

        #pragma unroll
        for (int mt = 0; mt < 5; mt++) {
            const int s2 = (((ks - mt) % 5) + 5) % 5;
            mma16816(aH[mt], R0[s2].x, R1[s2].x, R2[s2].x, R0[s2].x, b0, b1);
            mma16816(aL[mt], R0[s2].y, R1[s2].y, R2[s2].y, R0[s2].y, b0, b1);
        }
    }

    // ---- epilogue: hi+lo, column combine via shfl, blend, store
    const float inv = 1.0f / (float)PP;
    float* ob = out + (size_t)b * TT + (size_t)(blk * SEGB + w) * PP;
    #pragma unroll
    for (int mt = 0; mt < 5; mt++) {
        float t0 = aH[mt][0] + aL[mt][0];
        float t1 = aH[mt][1] + aL[mt][1];
        float t2 = aH[mt][2] + aL[mt][2];
        float t3 = aH[mt][3] + aL[mt][3];
        float s0 = t0 + __shfl_down_sync(0xffffffffu, t0, 1);
        float s1 = t1 + __shfl_down_sync(0xffffffffu, t1, 1);
        float s2 = t2 + __shfl_down_sync(0xffffffffu, t2, 1);
        float s3 = t3 + __shfl_down_sync(0xffffffffu, t3, 1);
        if (tg == 0) {
            int p = 16 * mt + g;
            ob[p]     = s0 + (float)p       * inv * s1;
            ob[p + 8] = s2 + (float)(p + 8) * inv * s3;
        }
    }
}

extern "C" void kernel_launch(void* const* d_in, const int* in_sizes, int n_in,
                              void* d_out, int out_size)
{
    const float* x = (const float*)d_in[0];
    const float* h = (const float*)d_in[1];
    float* out = (float*)d_out;
    (void)in_sizes; (void)n_in; (void)out_size;

    dim3 grid(NB / SEGB, 8);   // 100 x 8 = 800 blocks
    azdf_mma<<<grid, NTH>>>(x, h, out);
}

// round 12
// speedup vs baseline: 1.2548x; 1.1777x over previous
#include <cuda_runtime.h>
#include <cuda_fp16.h>
#include <stdint.h>

// AllZeroDigitalFilter via fp16 tensor cores; warp = full segment (80 rows).
// Toeplitz diagonal double-ring (F0/F2, a1(d) = F2[d-1]) -> 2 LDS.64 per diag,
// one-step software pipeline (prefetch diag ks+1 + B ks+1 during step ks),
// 4 segments per 128-thread block for occupancy.
// C[80x8] = A[80x256] * B[256x8]; A[p,k] = x[n*80+p-k];
// B cols = [h0_hi, d_hi, h0_lo, d_lo, 0..0]; accH = A_hi*B, accL = A_lo*B;
// out[p] = (col0+col2) + (p/80) * (col1+col3).

#define NB   800
#define PP   80
#define TAPS 256
#define TT   (NB * PP)
#define SEGB 4                 // segments (=warps) per block
#define NTH  (SEGB * 32)       // 128
#define WLEN 576               // staged reversed-window floats (need i <= 574)
#define NPAIR 287              // pair entries filled (v <= 286)
#define AP   296               // sA stride per parity (covers prefetch over-read)

__device__ __forceinline__ uint32_t packh2(__half lo, __half hi) {
    __half2 t = __halves2half2(lo, hi);
    return *reinterpret_cast<uint32_t*>(&t);
}

__device__ __forceinline__ void mma16816(float* c,
    uint32_t a0, uint32_t a1, uint32_t a2, uint32_t a3,
    uint32_t b0, uint32_t b1)
{
    asm volatile(
        "mma.sync.aligned.m16n8k16.row.col.f32.f16.f16.f32 "
        "{%0,%1,%2,%3}, {%4,%5,%6,%7}, {%8,%9}, {%0,%1,%2,%3};"
        : "+f"(c[0]), "+f"(c[1]), "+f"(c[2]), "+f"(c[3])
        : "r"(a0), "r"(a1), "r"(a2), "r"(a3), "r"(b0), "r"(b1));
}

#define SLOT(d) ((((d) % 6) + 6) % 6)

__global__ __launch_bounds__(NTH, 5)
void azdf_mma(const float* __restrict__ x,
              const float* __restrict__ h,
              float* __restrict__ out)
{
    __shared__ float swf[WLEN];           // swf[i] = x[blk*320 + 319 - i]
    __shared__ uint2 sA[2][AP];           // [parity][v] : {hi pair, lo pair}
    __shared__ uint2 sB[SEGB][4][17][4];  // [seg][col][ks(+pad)][tg] : {b0, b1}

    const int tid = threadIdx.x;
    const int b   = blockIdx.y;
    const int blk = blockIdx.x;

    // ---- stage reversed window (OOB -> 0)
    {
        const float* xb = x + (size_t)b * TT;
        const int gb = blk * (SEGB * PP) + (SEGB * PP - 1);
        for (int i = tid; i < WLEN; i += NTH) {
            int gt = gb - i;
            swf[i] = (gt >= 0) ? xb[gt] : 0.0f;
        }
    }
    // ---- stage B fragments (cols: 0=h0_hi 1=d_hi 2=h0_lo 3=d_lo)
    for (int e = tid; e < SEGB * 4 * 16 * 4; e += NTH) {
        int tg  = e & 3;
        int ks  = (e >> 2) & 15;
        int col = (e >> 6) & 3;
        int seg = e >> 8;
        int n   = blk * SEGB + seg;
        int nn  = (n + 1 < NB) ? (n + 1) : (NB - 1);
        const float* h0p = h + ((size_t)b * NB + n)  * TAPS;
        const float* h1p = h + ((size_t)b * NB + nn) * TAPS;
        const int filt = col & 1, part = col >> 1;
        const int kb = ks * 16 + 2 * tg;
        __half q[4];
        #pragma unroll
        for (int j = 0; j < 4; j++) {
            int k = kb + ((j >> 1) ? 8 : 0) + (j & 1);
            float a = h0p[k];
            float v = filt ? (h1p[k] - a) : a;
            __half vh = __float2half_rn(v);
            q[j] = part ? __float2half_rn(v - __half2float(vh)) : vh;
        }
        sB[seg][col][ks][tg] = make_uint2(packh2(q[0], q[1]), packh2(q[2], q[3]));
    }
    __syncthreads();

    // ---- fused parity pair arrays: E[v]={w2v,w2v+1}, O[v]={w2v+1,w2v+2}
    for (int v = tid; v < NPAIR; v += NTH) {
        float f0 = swf[2*v], f1 = swf[2*v+1], f2 = swf[2*v+2];
        __half h0 = __float2half_rn(f0), h1 = __float2half_rn(f1), h2 = __float2half_rn(f2);
        __half l0 = __float2half_rn(f0 - __half2float(h0));
        __half l1 = __float2half_rn(f1 - __half2float(h1));
        __half l2 = __float2half_rn(f2 - __half2float(h2));
        sA[0][v] = make_uint2(packh2(h0, h1), packh2(l0, l1));
        sA[1][v] = make_uint2(packh2(h1, h2), packh2(l1, l2));
    }
    __syncthreads();

    // ---- compute: warp w -> segment blk*SEGB + w
    const int w    = tid >> 5;
    const int lane = tid & 31;
    const int g    = lane >> 2;
    const int tg   = lane & 3;

    // A-frag pair index: frag(d): a0 = pA[v0+8d], a1 = pA[v0+8d-4], a2 = pA[v0+8d+4]
    // with identity a1(d) = a2(d-1).  L0 = (SEGB*80-1) - 80w - g + 2tg.
    const int L0 = (SEGB * PP - 1) - PP * w - g + 2 * tg;
    const int ph = L0 & 1;
    const int v0 = L0 >> 1;
    const uint2* pA = &sA[ph][0];
    const uint2* pB = &sB[w][g & 3][0][tg];

    float aH[5][4] = {};
    float aL[5][4] = {};

    // rings: F0[slot(d)] = pA[v0+8d], F2[slot(d)] = pA[v0+8d+4]
    uint2 F0[6], F2[6];
    #pragma unroll
    for (int d = -5; d <= 0; d++) F2[SLOT(d)] = pA[v0 + 8 * d + 4];
    #pragma unroll
    for (int d = -4; d <= 0; d++) F0[SLOT(d)] = pA[v0 + 8 * d];

    uint2 breg = pB[0];

    #pragma unroll
    for (int ks = 0; ks < 16; ks++) {
        // prefetch diag ks+1 and B(ks+1) (over-reads land in pads / unused slots)
        const int dn = ks + 1;
        uint2 nF0 = pA[v0 + 8 * dn];
        uint2 nF2 = pA[v0 + 8 * dn + 4];
        uint2 nB  = pB[(ks + 1) * 4];

        uint32_t b0 = 0u, b1 = 0u;
        if (g < 4) { b0 = breg.x; b1 = breg.y; }

        #pragma unroll
        for (int mt = 0; mt < 5; mt++) {
            const int d = ks - mt;
            const uint2 A0 = F0[SLOT(d)];
            const uint2 A1 = F2[SLOT(d - 1)];
            const uint2 A2 = F2[SLOT(d)];
            mma16816(aH[mt], A0.x, A1.x, A2.x, A0.x, b0, b1);
            mma16816(aL[mt], A0.y, A1.y, A2.y, A0.y, b0, b1);
        }

        F0[SLOT(dn)] = nF0;
        F2[SLOT(dn)] = nF2;
        breg = nB;
    }

    // ---- epilogue: hi+lo, column combine via shfl, blend, store
    const float inv = 1.0f / (float)PP;
    float* ob = out + (size_t)b * TT + (size_t)(blk * SEGB + w) * PP;
    #pragma unroll
    for (int mt = 0; mt < 5; mt++) {
        float t0 = aH[mt][0] + aL[mt][0];
        float t1 = aH[mt][1] + aL[mt][1];
        float t2 = aH[mt][2] + aL[mt][2];
        float t3 = aH[mt][3] + aL[mt][3];
        float s0 = t0 + __shfl_down_sync(0xffffffffu, t0, 1);
        float s1 = t1 + __shfl_down_sync(0xffffffffu, t1, 1);
        float s2 = t2 + __shfl_down_sync(0xffffffffu, t2, 1);
        float s3 = t3 + __shfl_down_sync(0xffffffffu, t3, 1);
        if (tg == 0) {
            int p = 16 * mt + g;
            ob[p]     = s0 + (float)p       * inv * s1;
            ob[p + 8] = s2 + (float)(p + 8) * inv * s3;
        }
    }
}

extern "C" void kernel_launch(void* const* d_in, const int* in_sizes, int n_in,
                              void* d_out, int out_size)
{
    const float* x = (const float*)d_in[0];
    const float* h = (const float*)d_in[1];
    float* out = (float*)d_out;
    (void)in_sizes; (void)n_in; (void)out_size;

    dim3 grid(NB / SEGB, 8);   // 200 x 8 = 1600 blocks
    azdf_mma<<<grid, NTH>>>(x, h, out);
}

// round 13
// speedup vs baseline: 1.3761x; 1.0967x over previous
#include <cuda_runtime.h>

// AllZeroDigitalFilter: FFMA2 (fma.rn.f32x2, measured rt=2 -> 2 FLOPs/issue)
// + R4 skeleton: K-split x2 (two 160-thread teams x 128 taps), prefetch-at-top.
// Pairing: Y_r = {y0_r, y1_r}; coeffs staged interleaved {h0[k], d[k]};
// window kept as 8 lane-duplicated pairs, slide by 4 via dup2 of prefetched float4.
// out[b, n*P+p] = y0 + (p/P)*y1.

#define TAPS 256
#define HALF 128
#define MM   255
#define PP   80
#define SEG  8
#define OUTB (SEG * PP)            // 640 outputs per block
#define RR   4
#define TEAM (OUTB / RR)           // 160 threads per team
#define NTHREADS (2 * TEAM)        // 320 threads
#define NB 800
#define BB 8
#define TT (NB * PP)
#define CPS 260                    // float2 stride per segment (h0,d interleaved + pad)

typedef unsigned long long u64;

__device__ __forceinline__ u64 dup2(float v) {
    u64 r; asm("mov.b64 %0, {%1,%1};" : "=l"(r) : "f"(v)); return r;
}
__device__ __forceinline__ void unpack2(u64 v, float& lo, float& hi) {
    asm("mov.b64 {%0,%1}, %2;" : "=f"(lo), "=f"(hi) : "l"(v));
}
__device__ __forceinline__ u64 ffma2(u64 a, u64 b, u64 c) {
    u64 d; asm("fma.rn.f32x2 %0, %1, %2, %3;" : "=l"(d) : "l"(a), "l"(b), "l"(c)); return d;
}

union F4U {
    float4 f4;
    struct { u64 lo, hi; } u;   // lo = {f4.x, f4.y}, hi = {f4.z, f4.w}
};

__global__ __launch_bounds__(NTHREADS)
void azdf_kernel(const float* __restrict__ x,
                 const float* __restrict__ h,
                 float* __restrict__ out)
{
    __shared__ float2 scp[SEG * CPS + 8];              // {h0,d} pairs (+pad)
    __shared__ __align__(16) float sx[8 + TAPS + OUTB]; // front pad + 896 window
    __shared__ float spart[TEAM * 20];                  // team-1 partials

    const int tid = threadIdx.x;
    const int b   = blockIdx.y;
    const int n0  = blockIdx.x * SEG;

    // ---- stage filters as interleaved {h0, d = h1 - h0}
    {
        const float* hb = h + (size_t)b * NB * TAPS;
        for (int idx = tid; idx < SEG * TAPS; idx += NTHREADS) {
            int s = idx >> 8, k = idx & 255;
            int n  = n0 + s;
            int nn = (n + 1 < NB) ? (n + 1) : (NB - 1);
            float a = hb[(size_t)n  * TAPS + k];
            float c = hb[(size_t)nn * TAPS + k];
            scp[s * CPS + k] = make_float2(a, c - a);
        }
    }
    // ---- stage x window: global [n0*P - M, n0*P - M + 895], OOB -> 0
    {
        const float* xb = x + (size_t)b * TT;
        const int gbase = n0 * PP - MM;
        for (int j = tid; j < TAPS + OUTB; j += NTHREADS) {
            int g = gbase + j;
            sx[8 + j] = (g >= 0 && g < TT) ? xb[g] : 0.0f;
        }
        if (tid < 8) sx[tid] = 0.0f;
    }
    __syncthreads();

    const int lane = (tid < TEAM) ? tid : (tid - TEAM);
    const int team = (tid < TEAM) ? 0 : 1;
    const int koff = team * HALF;
    const int pout = lane * RR;
    const int s    = lane / (PP / RR);                 // lane/20
    const float2* cp2 = scp + s * CPS + koff;
    const float*  wb  = sx + 8 + pout - koff;

    // accumulators: Y_r = {y0_r, y1_r}
    u64 Y0 = 0ull, Y1 = 0ull, Y2 = 0ull, Y3 = 0ull;

    // window dup-pairs: D[i] = {W,W}, W = wb[252 - 4*kk + i]
    u64 D0, D1, D2, D3, D4, D5, D6, D7;
    {
        float4 t0 = *(const float4*)(wb + 252);
        float4 t1 = *(const float4*)(wb + 256);
        D0 = dup2(t0.x); D1 = dup2(t0.y); D2 = dup2(t0.z); D3 = dup2(t0.w);
        D4 = dup2(t1.x); D5 = dup2(t1.y); D6 = dup2(t1.z); D7 = dup2(t1.w);
    }
    // coefficient quads for current iteration (taps 4kk .. 4kk+3), double buffered
    F4U ca, cb, na, nb_;
    ca.f4 = *(const float4*)(cp2 + 0);
    cb.f4 = *(const float4*)(cp2 + 2);

    #pragma unroll 4
    for (int kk = 0; kk < HALF / 4; kk++) {
        // ---- prefetch next window quad + next coeff quads (over-reads land in pads)
        float4 nw = *(const float4*)(wb + 248 - 4 * kk);
        na.f4  = *(const float4*)(cp2 + 4 * kk + 4);
        nb_.f4 = *(const float4*)(cp2 + 4 * kk + 6);

        // ---- 16 FFMA2 = 32 FMAs; tap u uses D[3-u+r] for outputs r=0..3
        Y0 = ffma2(D3, ca.u.lo, Y0); Y1 = ffma2(D4, ca.u.lo, Y1);   // u=0
        Y2 = ffma2(D5, ca.u.lo, Y2); Y3 = ffma2(D6, ca.u.lo, Y3);
        Y0 = ffma2(D2, ca.u.hi, Y0); Y1 = ffma2(D3, ca.u.hi, Y1);   // u=1
        Y2 = ffma2(D4, ca.u.hi, Y2); Y3 = ffma2(D5, ca.u.hi, Y3);
        Y0 = ffma2(D1, cb.u.lo, Y0); Y1 = ffma2(D2, cb.u.lo, Y1);   // u=2
        Y2 = ffma2(D3, cb.u.lo, Y2); Y3 = ffma2(D4, cb.u.lo, Y3);
        Y0 = ffma2(D0, cb.u.hi, Y0); Y1 = ffma2(D1, cb.u.hi, Y1);   // u=3
        Y2 = ffma2(D2, cb.u.hi, Y2); Y3 = ffma2(D3, cb.u.hi, Y3);

        // ---- slide by 4 + commit coeff double buffer
        D4 = D0; D5 = D1; D6 = D2; D7 = D3;
        D0 = dup2(nw.x); D1 = dup2(nw.y); D2 = dup2(nw.z); D3 = dup2(nw.w);
        ca = na; cb = nb_;
    }
    (void)D7;

    float y00, y10, y01, y11, y02, y12, y03, y13;
    unpack2(Y0, y00, y10); unpack2(Y1, y01, y11);
    unpack2(Y2, y02, y12); unpack2(Y3, y03, y13);

    if (team == 1) {
        float* sp = spart + lane * 20;
        ((float4*)sp)[0] = make_float4(y00, y01, y02, y03);
        ((float4*)sp)[1] = make_float4(y10, y11, y12, y13);
    }
    __syncthreads();
    if (team == 0) {
        const float* sp = spart + lane * 20;
        float4 p0 = ((const float4*)sp)[0];
        float4 p1 = ((const float4*)sp)[1];
        y00 += p0.x; y01 += p0.y; y02 += p0.z; y03 += p0.w;
        y10 += p1.x; y11 += p1.y; y12 += p1.z; y13 += p1.w;

        const float pb  = (float)(pout - s * PP);
        const float inv = 1.0f / (float)PP;
        float4 o;
        o.x = y00 + (pb + 0.0f) * inv * y10;
        o.y = y01 + (pb + 1.0f) * inv * y11;
        o.z = y02 + (pb + 2.0f) * inv * y12;
        o.w = y03 + (pb + 3.0f) * inv * y13;
        *(float4*)(out + (size_t)b * TT + n0 * PP + pout) = o;
    }
}

extern "C" void kernel_launch(void* const* d_in, const int* in_sizes, int n_in,
                              void* d_out, int out_size)
{
    const float* x = (const float*)d_in[0];
    const float* h = (const float*)d_in[1];
    float* out = (float*)d_out;
    (void)in_sizes; (void)n_in; (void)out_size;

    dim3 grid(NB / SEG, BB);   // 100 x 8 = 800 blocks
    azdf_kernel<<<grid, NTHREADS>>>(x, h, out);
}

// round 14
// speedup vs baseline: 1.5209x; 1.1052x over previous
#include <cuda_runtime.h>

// AllZeroDigitalFilter, scalar FFMA, overhead-minimized.
//   out[b, n*P+p] = y0 + (p/P)*y1 ; y0 = x*h0, y1 = x*(h1-h0)
// K-split x2 (two 160-thread teams x 128 taps), RR=4 outputs/thread,
// 8-tap inner iterations: 64 FFMA + 6 LDS.128 per iter; 12-float window array
// with single-quad carry (renamed by ptxas), prefetch one iter ahead.

#define TAPS 256
#define HALF 128
#define MM   255
#define PP   80
#define SEG  8
#define OUTB (SEG * PP)            // 640 outputs per block
#define RR   4
#define TEAM (OUTB / RR)           // 160 threads per team
#define NTHREADS (2 * TEAM)        // 320 threads
#define FSTRIDE (2 * TAPS + 8)     // h0[256] | d[256] | pad8
#define NB 800
#define BB 8
#define TT (NB * PP)

__global__ __launch_bounds__(NTHREADS)
void azdf_kernel(const float* __restrict__ x,
                 const float* __restrict__ h,
                 float* __restrict__ out)
{
    __shared__ float sf[SEG * FSTRIDE];            // 16.6 KB filters (h0 | d)
    __shared__ __align__(16) float sx[8 + TAPS + OUTB];  // 3.6 KB window (front pad)
    __shared__ float spart[TEAM * 20];             // team-1 partials

    const int tid = threadIdx.x;
    const int b   = blockIdx.y;
    const int n0  = blockIdx.x * SEG;

    // ---- stage filters: h0 and d = h1-h0 per segment
    {
        const float4* hb = (const float4*)(h + (size_t)b * NB * TAPS);
        for (int idx = tid; idx < SEG * (TAPS / 4); idx += NTHREADS) {
            int s  = idx >> 6;
            int k4 = idx & 63;
            int n  = n0 + s;
            int nn = (n + 1 < NB) ? (n + 1) : (NB - 1);
            float4 a = hb[n  * (TAPS / 4) + k4];
            float4 c = hb[nn * (TAPS / 4) + k4];
            float* f0 = sf + s * FSTRIDE;
            float* f1 = f0 + TAPS;
            f0[k4 * 4 + 0] = a.x; f0[k4 * 4 + 1] = a.y;
            f0[k4 * 4 + 2] = a.z; f0[k4 * 4 + 3] = a.w;
            f1[k4 * 4 + 0] = c.x - a.x; f1[k4 * 4 + 1] = c.y - a.y;
            f1[k4 * 4 + 2] = c.z - a.z; f1[k4 * 4 + 3] = c.w - a.w;
        }
    }
    // ---- stage x window: global [n0*P - M, n0*P - M + 895], OOB -> 0
    {
        const float* xb = x + (size_t)b * TT;
        const int gbase = n0 * PP - MM;
        for (int j = tid; j < TAPS + OUTB; j += NTHREADS) {
            int g = gbase + j;
            sx[8 + j] = (g >= 0 && g < TT) ? xb[g] : 0.0f;
        }
        if (tid < 8) sx[tid] = 0.0f;
    }
    __syncthreads();

    const int lane = (tid < TEAM) ? tid : (tid - TEAM);
    const int team = (tid < TEAM) ? 0 : 1;
    const int koff = team * HALF;
    const int pout = lane * RR;
    const int s    = lane / (PP / RR);             // lane/20
    const float* f0  = sf + s * FSTRIDE + koff;
    const float* f1  = f0 + TAPS;
    const float* wb  = sx + 8 + pout - koff;

    float a00 = 0.f, a01 = 0.f, a02 = 0.f, a03 = 0.f;   // conv h0
    float a10 = 0.f, a11 = 0.f, a12 = 0.f, a13 = 0.f;   // conv d

    // Window: W[i] = wb[248 - 8*kk + i], i = 0..11 (tap u, output r uses W[7-u+r])
    float W[12];
    {
        float4 t0 = *(const float4*)(wb + 248);
        float4 t1 = *(const float4*)(wb + 252);
        float4 t2 = *(const float4*)(wb + 256);
        W[0]=t0.x; W[1]=t0.y; W[2]=t0.z; W[3]=t0.w;
        W[4]=t1.x; W[5]=t1.y; W[6]=t1.z; W[7]=t1.w;
        W[8]=t2.x; W[9]=t2.y; W[10]=t2.z; W[11]=t2.w;
    }

    #pragma unroll 4
    for (int kk = 0; kk < HALF / 8; kk++) {
        // ---- prefetch next iteration's window quads (kk=15 over-read lands in pad)
        float4 nw0 = *(const float4*)(wb + 244 - 8 * kk);   // next W[4..7]
        float4 nw1 = *(const float4*)(wb + 240 - 8 * kk);   // next W[0..3]

        // ---- current coefficients (8 taps)
        float4 c0a = *(const float4*)(f0 + 8 * kk);
        float4 c0b = *(const float4*)(f0 + 8 * kk + 4);
        float4 c1a = *(const float4*)(f1 + 8 * kk);
        float4 c1b = *(const float4*)(f1 + 8 * kk + 4);

        // ---- 64 FFMA: tap u (0..7), output r uses W[7-u+r]
        a00 += W[7] * c0a.x; a01 += W[8] * c0a.x; a02 += W[9] * c0a.x; a03 += W[10] * c0a.x;
        a10 += W[7] * c1a.x; a11 += W[8] * c1a.x; a12 += W[9] * c1a.x; a13 += W[10] * c1a.x;
        a00 += W[6] * c0a.y; a01 += W[7] * c0a.y; a02 += W[8] * c0a.y; a03 += W[9]  * c0a.y;
        a10 += W[6] * c1a.y; a11 += W[7] * c1a.y; a12 += W[8] * c1a.y; a13 += W[9]  * c1a.y;
        a00 += W[5] * c0a.z; a01 += W[6] * c0a.z; a02 += W[7] * c0a.z; a03 += W[8]  * c0a.z;
        a10 += W[5] * c1a.z; a11 += W[6] * c1a.z; a12 += W[7] * c1a.z; a13 += W[8]  * c1a.z;
        a00 += W[4] * c0a.w; a01 += W[5] * c0a.w; a02 += W[6] * c0a.w; a03 += W[7]  * c0a.w;
        a10 += W[4] * c1a.w; a11 += W[5] * c1a.w; a12 += W[6] * c1a.w; a13 += W[7]  * c1a.w;
        a00 += W[3] * c0b.x; a01 += W[4] * c0b.x; a02 += W[5] * c0b.x; a03 += W[6]  * c0b.x;
        a10 += W[3] * c1b.x; a11 += W[4] * c1b.x; a12 += W[5] * c1b.x; a13 += W[6]  * c1b.x;
        a00 += W[2] * c0b.y; a01 += W[3] * c0b.y; a02 += W[4] * c0b.y; a03 += W[5]  * c0b.y;
        a10 += W[2] * c1b.y; a11 += W[3] * c1b.y; a12 += W[4] * c1b.y; a13 += W[5]  * c1b.y;
        a00 += W[1] * c0b.z; a01 += W[2] * c0b.z; a02 += W[3] * c0b.z; a03 += W[4]  * c0b.z;
        a10 += W[1] * c1b.z; a11 += W[2] * c1b.z; a12 += W[3] * c1b.z; a13 += W[4]  * c1b.z;
        a00 += W[0] * c0b.w; a01 += W[1] * c0b.w; a02 += W[2] * c0b.w; a03 += W[3]  * c0b.w;
        a10 += W[0] * c1b.w; a11 += W[1] * c1b.w; a12 += W[2] * c1b.w; a13 += W[3]  * c1b.w;

        // ---- slide window by 8: surviving quad W[0..3] -> W[8..11] (renamed)
        W[8]  = W[0]; W[9]  = W[1]; W[10] = W[2]; W[11] = W[3];
        W[4]  = nw0.x; W[5]  = nw0.y; W[6]  = nw0.z; W[7]  = nw0.w;
        W[0]  = nw1.x; W[1]  = nw1.y; W[2]  = nw1.z; W[3]  = nw1.w;
    }

    if (team == 1) {
        float* sp = spart + lane * 20;
        ((float4*)sp)[0] = make_float4(a00, a01, a02, a03);
        ((float4*)sp)[1] = make_float4(a10, a11, a12, a13);
    }
    __syncthreads();
    if (team == 0) {
        const float* sp = spart + lane * 20;
        float4 p0 = ((const float4*)sp)[0];
        float4 p1 = ((const float4*)sp)[1];
        a00 += p0.x; a01 += p0.y; a02 += p0.z; a03 += p0.w;
        a10 += p1.x; a11 += p1.y; a12 += p1.z; a13 += p1.w;

        const float pb  = (float)(pout - s * PP);
        const float inv = 1.0f / (float)PP;
        float4 o;
        o.x = a00 + (pb + 0.0f) * inv * a10;
        o.y = a01 + (pb + 1.0f) * inv * a11;
        o.z = a02 + (pb + 2.0f) * inv * a12;
        o.w = a03 + (pb + 3.0f) * inv * a13;
        *(float4*)(out + (size_t)b * TT + n0 * PP + pout) = o;
    }
}

extern "C" void kernel_launch(void* const* d_in, const int* in_sizes, int n_in,
                              void* d_out, int out_size)
{
    const float* x = (const float*)d_in[0];
    const float* h = (const float*)d_in[1];
    float* out = (float*)d_out;
    (void)in_sizes; (void)n_in; (void)out_size;

    dim3 grid(NB / SEG, BB);   // 100 x 8 = 800 blocks
    azdf_kernel<<<grid, NTHREADS>>>(x, h, out);
}